// round 7
// baseline (speedup 1.0000x reference)
#include <cuda_runtime.h>
#include <cstdint>
#include <math.h>

// Problem dims
#define B_   64
#define S_   512
#define I_   256
#define H_   512
#define G4H  2048          // 4*H
#define KTOT 768           // I + H
#define GRID 128           // CTAs (persistent, 1/SM); each owns 4 hidden indices
#define NTH  256

// ---------------- static device scratch (allocation-free rule) ----------------
__device__ __align__(16) float g_WU2[KTOT * G4H * 2];  // [k][col] duplicated pairs {w,w}
__device__ __align__(16) float g_xT [S_ * I_ * B_];     // [t][k][b]
__device__ __align__(16) float g_hT [H_ * B_];          // [hidden][b]
__device__ unsigned g_bar_cnt = 0;
__device__ volatile unsigned g_bar_sense = 0;

// SMEM layout: x slice [256][64] | h [512][64] | gates [16][64] | 2 mbarriers
#define SMEM_X_FLOATS (I_ * B_)          // 16384
#define SMEM_H_FLOATS (H_ * B_)          // 32768
#define SMEM_G_FLOATS (16 * B_)          // 1024
#define SMEM_BYTES ((SMEM_X_FLOATS + SMEM_H_FLOATS + SMEM_G_FLOATS) * 4 + 16)

// ---------------- PTX helpers ----------------
__device__ __forceinline__ unsigned sm2u(const void* p) {
    unsigned a;
    asm("{ .reg .u64 t; cvta.to.shared.u64 t, %1; cvt.u32.u64 %0, t; }"
        : "=r"(a) : "l"(p));
    return a;
}
__device__ __forceinline__ void mbar_init(unsigned a, unsigned c) {
    asm volatile("mbarrier.init.shared.b64 [%0], %1;" :: "r"(a), "r"(c) : "memory");
}
__device__ __forceinline__ void mbar_expect(unsigned a, unsigned bytes) {
    asm volatile("mbarrier.arrive.expect_tx.shared.b64 _, [%0], %1;"
                 :: "r"(a), "r"(bytes) : "memory");
}
__device__ __forceinline__ void bulk_g2s(unsigned dst, const void* src,
                                         unsigned bytes, unsigned mbar) {
    asm volatile(
        "cp.async.bulk.shared::cluster.global.mbarrier::complete_tx::bytes "
        "[%0], [%1], %2, [%3];"
        :: "r"(dst), "l"(src), "r"(bytes), "r"(mbar) : "memory");
}
__device__ __forceinline__ void mbar_wait(unsigned a, unsigned ph) {
    unsigned done = 0;
    while (!done) {
        asm volatile(
            "{ .reg .pred p; "
            "mbarrier.try_wait.parity.acquire.cta.shared::cta.b64 p, [%1], %2, 0x989680; "
            "selp.b32 %0, 1, 0, p; }"
            : "=r"(done) : "r"(a), "r"(ph) : "memory");
    }
}
__device__ __forceinline__ void fma2(unsigned long long& acc,
                                     unsigned long long a, unsigned long long b) {
    // packed fp32x2 FMA (Blackwell): 2 lane-FMAs per instruction
    asm("fma.rn.f32x2 %0, %1, %2, %0;" : "+l"(acc) : "l"(a), "l"(b));
}

// ---------------- prep kernel: build duplicated [W;U] weights, zero h ----------------
__global__ void k_prep(const float* __restrict__ W, const float* __restrict__ U) {
    int idx = blockIdx.x * blockDim.x + threadIdx.x;   // over KTOT*G4H = 1,572,864
    if (idx < KTOT * G4H) {
        int k = idx >> 11;        // /2048
        int c = idx & 2047;
        float w = (k < I_) ? W[k * G4H + c] : U[(k - I_) * G4H + c];
        reinterpret_cast<float2*>(g_WU2)[idx] = make_float2(w, w);
    }
    if (idx < H_ * B_) g_hT[idx] = 0.0f;
}

// ---------------- transpose x[b][t][k] -> g_xT[t][k][b] ----------------
__global__ void k_xT(const float* __restrict__ x) {
    __shared__ float ts[64][65];
    int t  = blockIdx.x;
    int k0 = blockIdx.y * 64;
    for (int i = threadIdx.x; i < 64 * 64; i += NTH) {
        int b = i >> 6, kk = i & 63;
        ts[b][kk] = x[(b * S_ + t) * I_ + k0 + kk];
    }
    __syncthreads();
    for (int i = threadIdx.x; i < 64 * 64; i += NTH) {
        int kk = i >> 6, b = i & 63;
        g_xT[(t * I_ + k0 + kk) * B_ + b] = ts[b][kk];
    }
}

// ---------------- persistent LSTM kernel ----------------
__global__ void __launch_bounds__(NTH, 1)
k_lstm(const float* __restrict__ bias, float* __restrict__ out) {
    extern __shared__ char smem[];
    float* smx = reinterpret_cast<float*>(smem);        // [256][64]
    float* smh = smx + SMEM_X_FLOATS;                   // [512][64]
    float* sg  = smh + SMEM_H_FLOATS;                   // [16][64]
    unsigned long long* mb =
        reinterpret_cast<unsigned long long*>(sg + SMEM_G_FLOATS);
    const unsigned mbx = sm2u(mb);
    const unsigned mbh = sm2u(mb + 1);
    const unsigned smx_u = sm2u(smx);
    const unsigned smh_u = sm2u(smh);

    const int tid = threadIdx.x;
    // GEMM mapping: 16 batch-groups x 16 gate-columns
    const int bg = tid & 15;            // batch group: b = bg*4 .. bg*4+3
    const int cg = tid >> 4;            // gate column: g = cg>>2, jl = cg&3
    const int colg = ((cg >> 2) * H_) + blockIdx.x * 4 + (cg & 3);
    const unsigned long long* wp =
        reinterpret_cast<const unsigned long long*>(g_WU2) + colg;
    // Update mapping: thread -> (jl, b); owns c state in a register
    const int jl = tid >> 6;            // 0..3
    const int bu = tid & 63;            // 0..63
    const int hcol = blockIdx.x * 4 + jl;
    float c_state = 0.0f;

    const float bs = bias[colg];
    unsigned long long bias2;
    asm("mov.b64 %0, {%1, %1};" : "=l"(bias2) : "f"(bs));

    if (tid == 0) {
        mbar_init(mbx, 1);
        mbar_init(mbh, 1);
        asm volatile("fence.proxy.async.shared::cta;" ::: "memory");
    }
    __syncthreads();
    if (tid == 0) {  // prefetch x slice for t=0
        mbar_expect(mbx, SMEM_X_FLOATS * 4);
        bulk_g2s(smx_u, g_xT, SMEM_X_FLOATS * 4, mbx);
    }

    for (int t = 0; t < S_; ++t) {
        const unsigned ph = (unsigned)(t & 1);

        // kick off h broadcast copy (overlaps with x-part compute)
        if (tid == 0) {
            mbar_expect(mbh, SMEM_H_FLOATS * 4);
            bulk_g2s(smh_u, g_hT, SMEM_H_FLOATS * 4, mbh);
        }

        unsigned long long a0 = bias2, a1 = bias2;   // (b0,b1) and (b2,b3)
        const unsigned long long* w = wp;

        // ---- x-part: k over I_, weights = W rows ----
        mbar_wait(mbx, ph);
        {
            const float* sp = smx + bg * 4;
            #pragma unroll 4
            for (int k = 0; k < I_; ++k) {
                ulonglong2 hv = *reinterpret_cast<const ulonglong2*>(sp);
                unsigned long long u = *w;
                sp += B_; w += G4H;
                fma2(a0, hv.x, u);
                fma2(a1, hv.y, u);
            }
        }
        // ---- h-part: k over H_, weights = U rows ----
        mbar_wait(mbh, ph);
        {
            const float* sp = smh + bg * 4;
            #pragma unroll 4
            for (int k = 0; k < H_; ++k) {
                ulonglong2 hv = *reinterpret_cast<const ulonglong2*>(sp);
                unsigned long long u = *w;
                sp += B_; w += G4H;
                fma2(a0, hv.x, u);
                fma2(a1, hv.y, u);
            }
        }

        // gate values -> smem exchange
        float4 gv;
        asm("mov.b64 {%0, %1}, %2;" : "=f"(gv.x), "=f"(gv.y) : "l"(a0));
        asm("mov.b64 {%0, %1}, %2;" : "=f"(gv.z), "=f"(gv.w) : "l"(a1));
        *reinterpret_cast<float4*>(sg + cg * B_ + bg * 4) = gv;
        __syncthreads();

        // prefetch next x slice (overlaps with update + barrier)
        if (tid == 0 && t + 1 < S_) {
            mbar_expect(mbx, SMEM_X_FLOATS * 4);
            bulk_g2s(smx_u, g_xT + (size_t)(t + 1) * I_ * B_,
                     SMEM_X_FLOATS * 4, mbx);
        }

        // ---- cell update for (bu, hcol) ----
        {
            float gi = sg[(0 * 4 + jl) * B_ + bu];
            float gf = sg[(1 * 4 + jl) * B_ + bu];
            float gg = sg[(2 * 4 + jl) * B_ + bu];
            float go = sg[(3 * 4 + jl) * B_ + bu];
            float iv = 1.0f / (1.0f + expf(-gi));
            float fv = 1.0f / (1.0f + expf(-gf));
            float gv2 = tanhf(gg);
            float ov = 1.0f / (1.0f + expf(-go));
            c_state = fv * c_state + iv * gv2;
            float hv2 = ov * tanhf(c_state);

            g_hT[hcol * B_ + bu] = hv2;                          // state for next step
            out[((size_t)bu * S_ + t) * H_ + hcol] = hv2;        // hidden_seq[b][t][h]
            if (t == S_ - 1) {
                size_t base = (size_t)B_ * S_ * H_;
                out[base + (size_t)bu * H_ + hcol] = hv2;                 // h_f
                out[base + (size_t)B_ * H_ + (size_t)bu * H_ + hcol] = c_state; // c_f
            }
        }

        // ---- grid barrier (sense-reversing; 512 toggles -> sense returns to 0) ----
        __syncthreads();
        if (tid == 0) {
            __threadfence();
            unsigned want = (unsigned)((t & 1) ^ 1);
            if (atomicAdd(&g_bar_cnt, 1u) == GRID - 1) {
                atomicExch(&g_bar_cnt, 0u);
                __threadfence();
                g_bar_sense = want;
            } else {
                while (g_bar_sense != want) { }
            }
            __threadfence();
        }
        __syncthreads();
    }
}

// ---------------- launch ----------------
extern "C" void kernel_launch(void* const* d_in, const int* in_sizes, int n_in,
                              void* d_out, int out_size) {
    const float* x = nullptr;
    const float* W = nullptr;
    const float* U = nullptr;
    const float* bias = nullptr;
    for (int i = 0; i < n_in; ++i) {
        switch (in_sizes[i]) {
            case B_ * S_ * I_: x    = (const float*)d_in[i]; break;  // 8388608
            case I_ * G4H:     W    = (const float*)d_in[i]; break;  // 524288
            case H_ * G4H:     U    = (const float*)d_in[i]; break;  // 1048576
            case G4H:          bias = (const float*)d_in[i]; break;  // 2048
            default: break;
        }
    }
    // fallback to positional order (x, W, U, bias) if sizes unexpected
    if (!x && n_in > 0)    x    = (const float*)d_in[0];
    if (!W && n_in > 1)    W    = (const float*)d_in[1];
    if (!U && n_in > 2)    U    = (const float*)d_in[2];
    if (!bias && n_in > 3) bias = (const float*)d_in[3];

    cudaFuncSetAttribute(k_lstm, cudaFuncAttributeMaxDynamicSharedMemorySize,
                         SMEM_BYTES);

    k_prep<<<(KTOT * G4H) / NTH, NTH>>>(W, U);      // 6144 blocks
    k_xT<<<dim3(S_, I_ / 64), NTH>>>(x);            // (512, 4)
    k_lstm<<<GRID, NTH, SMEM_BYTES>>>(bias, (float*)d_out);
}

// round 8
// speedup vs baseline: 1.0307x; 1.0307x over previous
#include <cuda_runtime.h>
#include <cstdint>
#include <math.h>

// Problem dims
#define B_   64
#define S_   512
#define I_   256
#define H_   512
#define G4H  2048          // 4*H
#define KTOT 768           // I + H
#define GRID 128           // CTAs (persistent, 1/SM); each owns 4 hidden indices
#define NTH  256

// ---------------- static device scratch (allocation-free rule) ----------------
__device__ __align__(16) float g_WU2[KTOT * G4H * 2];  // [k][col] duplicated pairs {w,w}
__device__ __align__(16) float g_xT [S_ * I_ * B_];     // [t][k][b]
__device__ __align__(16) float g_hT [H_ * B_];          // [hidden][b]
__device__ unsigned g_bar_cnt = 0;
__device__ volatile unsigned g_bar_sense = 0;

// SMEM layout: x slice [256][64] | h [512][64] | gates [16][64] | 2 mbarriers
#define SMEM_X_FLOATS (I_ * B_)          // 16384
#define SMEM_H_FLOATS (H_ * B_)          // 32768
#define SMEM_G_FLOATS (16 * B_)          // 1024
#define SMEM_BYTES ((SMEM_X_FLOATS + SMEM_H_FLOATS + SMEM_G_FLOATS) * 4 + 16)

// ---------------- PTX helpers ----------------
__device__ __forceinline__ unsigned sm2u(const void* p) {
    unsigned a;
    asm("{ .reg .u64 t; cvta.to.shared.u64 t, %1; cvt.u32.u64 %0, t; }"
        : "=r"(a) : "l"(p));
    return a;
}
__device__ __forceinline__ void mbar_init(unsigned a, unsigned c) {
    asm volatile("mbarrier.init.shared.b64 [%0], %1;" :: "r"(a), "r"(c) : "memory");
}
__device__ __forceinline__ void mbar_expect(unsigned a, unsigned bytes) {
    asm volatile("mbarrier.arrive.expect_tx.shared.b64 _, [%0], %1;"
                 :: "r"(a), "r"(bytes) : "memory");
}
__device__ __forceinline__ void bulk_g2s(unsigned dst, const void* src,
                                         unsigned bytes, unsigned mbar) {
    asm volatile(
        "cp.async.bulk.shared::cluster.global.mbarrier::complete_tx::bytes "
        "[%0], [%1], %2, [%3];"
        :: "r"(dst), "l"(src), "r"(bytes), "r"(mbar) : "memory");
}
__device__ __forceinline__ void mbar_wait(unsigned a, unsigned ph) {
    unsigned done = 0;
    while (!done) {
        asm volatile(
            "{ .reg .pred p; "
            "mbarrier.try_wait.parity.acquire.cta.shared::cta.b64 p, [%1], %2, 0x989680; "
            "selp.b32 %0, 1, 0, p; }"
            : "=r"(done) : "r"(a), "r"(ph) : "memory");
    }
}
__device__ __forceinline__ void fma2(unsigned long long& acc,
                                     unsigned long long a, unsigned long long b) {
    // packed fp32x2 FMA (Blackwell): 2 lane-FMAs per instruction
    asm("fma.rn.f32x2 %0, %1, %2, %0;" : "+l"(acc) : "l"(a), "l"(b));
}

// ---------------- prep kernel: build duplicated [W;U] weights, zero h ----------------
__global__ void k_prep(const float* __restrict__ W, const float* __restrict__ U) {
    int idx = blockIdx.x * blockDim.x + threadIdx.x;   // over KTOT*G4H = 1,572,864
    if (idx < KTOT * G4H) {
        int k = idx >> 11;        // /2048
        int c = idx & 2047;
        float w = (k < I_) ? W[k * G4H + c] : U[(k - I_) * G4H + c];
        reinterpret_cast<float2*>(g_WU2)[idx] = make_float2(w, w);
    }
    if (idx < H_ * B_) g_hT[idx] = 0.0f;
}

// ---------------- transpose x[b][t][k] -> g_xT[t][k][b] ----------------
__global__ void k_xT(const float* __restrict__ x) {
    __shared__ float ts[64][65];
    int t  = blockIdx.x;
    int k0 = blockIdx.y * 64;
    for (int i = threadIdx.x; i < 64 * 64; i += NTH) {
        int b = i >> 6, kk = i & 63;
        ts[b][kk] = x[(b * S_ + t) * I_ + k0 + kk];
    }
    __syncthreads();
    for (int i = threadIdx.x; i < 64 * 64; i += NTH) {
        int kk = i >> 6, b = i & 63;
        g_xT[(t * I_ + k0 + kk) * B_ + b] = ts[b][kk];
    }
}

// ---------------- persistent LSTM kernel ----------------
__global__ void __launch_bounds__(NTH, 1)
k_lstm(const float* __restrict__ bias, float* __restrict__ out) {
    extern __shared__ char smem[];
    float* smx = reinterpret_cast<float*>(smem);        // [256][64]
    float* smh = smx + SMEM_X_FLOATS;                   // [512][64]
    float* sg  = smh + SMEM_H_FLOATS;                   // [16][64]
    unsigned long long* mb =
        reinterpret_cast<unsigned long long*>(sg + SMEM_G_FLOATS);
    const unsigned mbx = sm2u(mb);
    const unsigned mbh = sm2u(mb + 1);
    const unsigned smx_u = sm2u(smx);
    const unsigned smh_u = sm2u(smh);

    const int tid = threadIdx.x;
    // GEMM mapping: 16 batch-groups x 16 gate-columns
    const int bg = tid & 15;            // batch group: b = bg*4 .. bg*4+3
    const int cg = tid >> 4;            // gate column: g = cg>>2, jl = cg&3
    const int colg = ((cg >> 2) * H_) + blockIdx.x * 4 + (cg & 3);
    const unsigned long long* wp =
        reinterpret_cast<const unsigned long long*>(g_WU2) + colg;
    // Update mapping: thread -> (jl, b); owns c state in a register
    const int jl = tid >> 6;            // 0..3
    const int bu = tid & 63;            // 0..63
    const int hcol = blockIdx.x * 4 + jl;
    float c_state = 0.0f;

    const float bs = bias[colg];
    unsigned long long bias2;
    asm("mov.b64 %0, {%1, %1};" : "=l"(bias2) : "f"(bs));

    if (tid == 0) {
        mbar_init(mbx, 1);
        mbar_init(mbh, 1);
        asm volatile("fence.proxy.async.shared::cta;" ::: "memory");
    }
    __syncthreads();
    if (tid == 0) {  // prefetch x slice for t=0
        mbar_expect(mbx, SMEM_X_FLOATS * 4);
        bulk_g2s(smx_u, g_xT, SMEM_X_FLOATS * 4, mbx);
    }

    for (int t = 0; t < S_; ++t) {
        const unsigned ph = (unsigned)(t & 1);

        // kick off h broadcast copy (overlaps with x-part compute)
        if (tid == 0) {
            mbar_expect(mbh, SMEM_H_FLOATS * 4);
            bulk_g2s(smh_u, g_hT, SMEM_H_FLOATS * 4, mbh);
        }

        unsigned long long a0 = bias2, a1 = bias2;   // (b0,b1) and (b2,b3)
        const unsigned long long* w = wp;

        // ---- x-part: k over I_, weights = W rows ----
        mbar_wait(mbx, ph);
        {
            const float* sp = smx + bg * 4;
            #pragma unroll 4
            for (int k = 0; k < I_; ++k) {
                ulonglong2 hv = *reinterpret_cast<const ulonglong2*>(sp);
                unsigned long long u = *w;
                sp += B_; w += G4H;
                fma2(a0, hv.x, u);
                fma2(a1, hv.y, u);
            }
        }
        // ---- h-part: k over H_, weights = U rows ----
        mbar_wait(mbh, ph);
        {
            const float* sp = smh + bg * 4;
            #pragma unroll 4
            for (int k = 0; k < H_; ++k) {
                ulonglong2 hv = *reinterpret_cast<const ulonglong2*>(sp);
                unsigned long long u = *w;
                sp += B_; w += G4H;
                fma2(a0, hv.x, u);
                fma2(a1, hv.y, u);
            }
        }

        // gate values -> smem exchange
        float4 gv;
        asm("mov.b64 {%0, %1}, %2;" : "=f"(gv.x), "=f"(gv.y) : "l"(a0));
        asm("mov.b64 {%0, %1}, %2;" : "=f"(gv.z), "=f"(gv.w) : "l"(a1));
        *reinterpret_cast<float4*>(sg + cg * B_ + bg * 4) = gv;
        __syncthreads();

        // prefetch next x slice (overlaps with update + barrier)
        if (tid == 0 && t + 1 < S_) {
            mbar_expect(mbx, SMEM_X_FLOATS * 4);
            bulk_g2s(smx_u, g_xT + (size_t)(t + 1) * I_ * B_,
                     SMEM_X_FLOATS * 4, mbx);
        }

        // ---- cell update for (bu, hcol) ----
        {
            float gi = sg[(0 * 4 + jl) * B_ + bu];
            float gf = sg[(1 * 4 + jl) * B_ + bu];
            float gg = sg[(2 * 4 + jl) * B_ + bu];
            float go = sg[(3 * 4 + jl) * B_ + bu];
            float iv = 1.0f / (1.0f + expf(-gi));
            float fv = 1.0f / (1.0f + expf(-gf));
            float gv2 = tanhf(gg);
            float ov = 1.0f / (1.0f + expf(-go));
            c_state = fv * c_state + iv * gv2;
            float hv2 = ov * tanhf(c_state);

            g_hT[hcol * B_ + bu] = hv2;                          // state for next step
            out[((size_t)bu * S_ + t) * H_ + hcol] = hv2;        // hidden_seq[b][t][h]
            if (t == S_ - 1) {
                size_t base = (size_t)B_ * S_ * H_;
                out[base + (size_t)bu * H_ + hcol] = hv2;                 // h_f
                out[base + (size_t)B_ * H_ + (size_t)bu * H_ + hcol] = c_state; // c_f
            }
        }

        // ---- grid barrier (sense-reversing; 512 toggles -> sense returns to 0) ----
        __syncthreads();
        if (tid == 0) {
            __threadfence();
            unsigned want = (unsigned)((t & 1) ^ 1);
            if (atomicAdd(&g_bar_cnt, 1u) == GRID - 1) {
                atomicExch(&g_bar_cnt, 0u);
                __threadfence();
                g_bar_sense = want;
            } else {
                while (g_bar_sense != want) { }
            }
            __threadfence();
        }
        __syncthreads();
    }
}

// ---------------- launch ----------------
extern "C" void kernel_launch(void* const* d_in, const int* in_sizes, int n_in,
                              void* d_out, int out_size) {
    const float* x = nullptr;
    const float* W = nullptr;
    const float* U = nullptr;
    const float* bias = nullptr;
    for (int i = 0; i < n_in; ++i) {
        switch (in_sizes[i]) {
            case B_ * S_ * I_: x    = (const float*)d_in[i]; break;  // 8388608
            case I_ * G4H:     W    = (const float*)d_in[i]; break;  // 524288
            case H_ * G4H:     U    = (const float*)d_in[i]; break;  // 1048576
            case G4H:          bias = (const float*)d_in[i]; break;  // 2048
            default: break;
        }
    }
    // fallback to positional order (x, W, U, bias) if sizes unexpected
    if (!x && n_in > 0)    x    = (const float*)d_in[0];
    if (!W && n_in > 1)    W    = (const float*)d_in[1];
    if (!U && n_in > 2)    U    = (const float*)d_in[2];
    if (!bias && n_in > 3) bias = (const float*)d_in[3];

    cudaFuncSetAttribute(k_lstm, cudaFuncAttributeMaxDynamicSharedMemorySize,
                         SMEM_BYTES);

    k_prep<<<(KTOT * G4H) / NTH, NTH>>>(W, U);      // 6144 blocks
    k_xT<<<dim3(S_, I_ / 64), NTH>>>(x);            // (512, 4)
    k_lstm<<<GRID, NTH, SMEM_BYTES>>>(bias, (float*)d_out);
}

// round 10
// speedup vs baseline: 1.9853x; 1.9262x over previous
#include <cuda_runtime.h>
#include <cstdint>
#include <math.h>

#define B_   64
#define S_   512
#define I_   256
#define H_   512
#define G4H  2048
#define KTOT 768
#define GRID 128
#define NTH  256

// SMEM float offsets
#define F_WU  12288            // [768][16]
#define F_X   (2*64*68)        // 2 x [64 b][68]
#define F_H   (64*516)         // [64 b][516]
#define F_G   (64*20)          // gate exchange, stride 20
#define SMEM_FLOATS (F_WU + F_X + F_H + F_G)
#define SMEM_BYTES  (SMEM_FLOATS*4 + 64)

__device__ __align__(16) float g_h[B_ * H_];   // h state [b][512]
__device__ unsigned g_bar_cnt = 0;
__device__ volatile unsigned g_bar_sense = 0;

// ---------- PTX helpers ----------
__device__ __forceinline__ unsigned sm2u(const void* p) {
    unsigned a;
    asm("{ .reg .u64 t; cvta.to.shared.u64 t, %1; cvt.u32.u64 %0, t; }" : "=r"(a) : "l"(p));
    return a;
}
__device__ __forceinline__ void mbar_init(unsigned a, unsigned c) {
    asm volatile("mbarrier.init.shared.b64 [%0], %1;" :: "r"(a), "r"(c) : "memory");
}
__device__ __forceinline__ void mbar_arrive_expect(unsigned a, unsigned bytes) {
    asm volatile("mbarrier.arrive.expect_tx.shared.b64 _, [%0], %1;"
                 :: "r"(a), "r"(bytes) : "memory");
}
__device__ __forceinline__ void bulk_g2s(unsigned dst, const void* src,
                                         unsigned bytes, unsigned mbar) {
    asm volatile("cp.async.bulk.shared::cluster.global.mbarrier::complete_tx::bytes "
                 "[%0], [%1], %2, [%3];"
                 :: "r"(dst), "l"(src), "r"(bytes), "r"(mbar) : "memory");
}
__device__ __forceinline__ void mbar_wait(unsigned a, unsigned ph) {
    unsigned done = 0;
    while (!done) {
        asm volatile("{ .reg .pred p; "
                     "mbarrier.try_wait.parity.acquire.cta.shared::cta.b64 p, [%1], %2, 0x989680; "
                     "selp.b32 %0, 1, 0, p; }"
                     : "=r"(done) : "r"(a), "r"(ph) : "memory");
    }
}
__device__ __forceinline__ void fma2(unsigned long long& acc,
                                     unsigned long long a, unsigned long long b) {
    asm("fma.rn.f32x2 %0, %1, %2, %0;" : "+l"(acc) : "l"(a), "l"(b));
}
// 4 k-steps: 1 batch value stream (float4) x 4 columns from SMEM weights
__device__ __forceinline__ void dot4(const float* __restrict__ xb,
                                     const float* __restrict__ wu,
                                     unsigned long long& a01, unsigned long long& a23) {
    float4 h4 = *reinterpret_cast<const float4*>(xb);
#pragma unroll
    for (int j = 0; j < 4; ++j) {
        float hv = (&h4.x)[j];
        unsigned long long hh;
        asm("mov.b64 %0, {%1, %1};" : "=l"(hh) : "f"(hv));
        ulonglong2 w = *reinterpret_cast<const ulonglong2*>(wu + j * 16);
        fma2(a01, hh, w.x);
        fma2(a23, hh, w.y);
    }
}

// ---------- init: zero h state ----------
__global__ void k_init() {
    int i = blockIdx.x * blockDim.x + threadIdx.x;
    if (i < B_ * H_) g_h[i] = 0.0f;
}

// ---------- persistent LSTM ----------
__global__ void __launch_bounds__(NTH, 1)
k_lstm(const float* __restrict__ x, const float* __restrict__ W,
       const float* __restrict__ U, const float* __restrict__ bias,
       float* __restrict__ out) {
    extern __shared__ float sm[];
    float* sWU = sm;                  // [768][16]
    float* sX  = sm + F_WU;           // 2 x [64][68]
    float* sH  = sX + F_X;            // [64][516]
    float* sG  = sH + F_H;            // [64][20]
    unsigned long long* mb = reinterpret_cast<unsigned long long*>(sG + F_G);
    const unsigned mbX0 = sm2u(mb + 0), mbX1 = sm2u(mb + 1);
    const unsigned mbH0 = sm2u(mb + 2);           // +8*c for chunk c
    const unsigned sX_u = sm2u(sX), sH_u = sm2u(sH);

    const int tid = threadIdx.x;
    const int blk = blockIdx.x;
    const int b   = tid >> 2;         // 0..63 (GEMM batch)
    const int cq  = tid & 3;          // gate 0..3
    const int bu  = tid >> 2;         // update batch
    const int jl  = tid & 3;          // update hidden sub-col
    const int hcol = blk * 4 + jl;
    float c_state = 0.0f;

    // ---- prologue: weights -> SMEM (once), mbar init ----
    if (tid == 0) {
        mbar_init(mbX0, 64); mbar_init(mbX1, 64);
        mbar_init(mbH0, 64); mbar_init(mbH0 + 8, 64);
        mbar_init(mbH0 + 16, 64); mbar_init(mbH0 + 24, 64);
        asm volatile("fence.proxy.async.shared::cta;" ::: "memory");
    }
    for (int i = tid; i < KTOT * 4; i += NTH) {   // i = k*4 + q
        int k = i >> 2, q = i & 3;
        int col = q * H_ + blk * 4;               // 16B-contiguous group
        float4 w = (k < I_)
            ? *reinterpret_cast<const float4*>(W + (size_t)k * G4H + col)
            : *reinterpret_cast<const float4*>(U + (size_t)(k - I_) * G4H + col);
        *reinterpret_cast<float4*>(sWU + k * 16 + q * 4) = w;
    }
    unsigned long long bias01, bias23;
    {
        float4 bv = *reinterpret_cast<const float4*>(bias + cq * H_ + blk * 4);
        asm("mov.b64 %0, {%1, %2};" : "=l"(bias01) : "f"(bv.x), "f"(bv.y));
        asm("mov.b64 %0, {%1, %2};" : "=l"(bias23) : "f"(bv.z), "f"(bv.w));
    }
    __syncthreads();

    // prologue x loads: chunks 0,1 of t=0
    if (tid < 128) {
        int c = tid >> 6, row = tid & 63;
        unsigned dst = sX_u + (unsigned)(c * (64 * 68) + row * 68) * 4u;
        const float* src = x + ((size_t)row * S_ + 0) * I_ + c * 64;
        mbar_arrive_expect(c ? mbX1 : mbX0, 256);
        bulk_g2s(dst, src, 256, c ? mbX1 : mbX0);
    }
    unsigned phx[2] = {0u, 0u};

    for (int t = 0; t < S_; ++t) {
        // ---- issue all 4 h-chunk copies (one 512B row-chunk per thread) ----
        {
            int c = tid >> 6, row = tid & 63;
            unsigned mbh = mbH0 + (unsigned)(c * 8);
            unsigned dst = sH_u + (unsigned)(row * 516 + c * 128) * 4u;
            const float* src = g_h + row * H_ + c * 128;
            mbar_arrive_expect(mbh, 512);
            bulk_g2s(dst, src, 512, mbh);
        }

        unsigned long long a01 = bias01, a23 = bias23;

        // ---- x-part: 4 chunks of 64 k, double-buffered ----
#pragma unroll
        for (int c = 0; c < 4; ++c) {
            const int m = c & 1;
            mbar_wait(m ? mbX1 : mbX0, phx[m]); phx[m] ^= 1u;
            const float* xb = sX + m * (64 * 68) + b * 68;
            const float* wu = sWU + (c * 64) * 16 + cq * 4;
#pragma unroll 4
            for (int kk = 0; kk < 64; kk += 4)
                dot4(xb + kk, wu + kk * 16, a01, a23);
            __syncthreads();                      // buffer m free
            int cr = (c + 2) & 3, tl = t + ((c + 2) >> 2);
            if (tid < 64 && tl < S_) {
                unsigned dst = sX_u + (unsigned)(m * (64 * 68) + tid * 68) * 4u;
                const float* src = x + ((size_t)tid * S_ + tl) * I_ + cr * 64;
                unsigned mbx = m ? mbX1 : mbX0;
                mbar_arrive_expect(mbx, 256);
                bulk_g2s(dst, src, 256, mbx);
            }
        }

        // ---- h-part: 4 chunks of 128 k ----
#pragma unroll
        for (int c = 0; c < 4; ++c) {
            mbar_wait(mbH0 + (unsigned)(c * 8), (unsigned)(t & 1));
            const float* hb = sH + b * 516 + c * 128;
            const float* wu = sWU + (I_ + c * 128) * 16 + cq * 4;
#pragma unroll 4
            for (int kk = 0; kk < 128; kk += 4)
                dot4(hb + kk, wu + kk * 16, a01, a23);
        }

        // ---- gate exchange ----
        float4 gv;
        asm("mov.b64 {%0, %1}, %2;" : "=f"(gv.x), "=f"(gv.y) : "l"(a01));
        asm("mov.b64 {%0, %1}, %2;" : "=f"(gv.z), "=f"(gv.w) : "l"(a23));
        *reinterpret_cast<float4*>(sG + b * 20 + cq * 4) = gv;
        __syncthreads();

        // ---- cell update: thread -> (bu, hcol) ----
        {
            float gi = sG[bu * 20 + 0 + jl];
            float gf = sG[bu * 20 + 4 + jl];
            float gg = sG[bu * 20 + 8 + jl];
            float go = sG[bu * 20 + 12 + jl];
            float iv = 1.0f / (1.0f + expf(-gi));
            float fv = 1.0f / (1.0f + expf(-gf));
            float gt = tanhf(gg);
            float ov = 1.0f / (1.0f + expf(-go));
            c_state = fv * c_state + iv * gt;
            float hv = ov * tanhf(c_state);

            g_h[bu * H_ + hcol] = hv;
            out[((size_t)bu * S_ + t) * H_ + hcol] = hv;
            if (t == S_ - 1) {
                size_t base = (size_t)B_ * S_ * H_;
                out[base + (size_t)bu * H_ + hcol] = hv;
                out[base + (size_t)B_ * H_ + (size_t)bu * H_ + hcol] = c_state;
            }
        }

        // ---- grid barrier (sense-reversing) ----
        __syncthreads();
        if (tid == 0) {
            __threadfence();
            unsigned want = (unsigned)((t & 1) ^ 1);
            if (atomicAdd(&g_bar_cnt, 1u) == GRID - 1) {
                atomicExch(&g_bar_cnt, 0u);
                __threadfence();
                g_bar_sense = want;
            } else {
                while (g_bar_sense != want) { }
            }
            __threadfence();
        }
        __syncthreads();
    }
}

// ---------- launch ----------
extern "C" void kernel_launch(void* const* d_in, const int* in_sizes, int n_in,
                              void* d_out, int out_size) {
    const float* x = nullptr; const float* W = nullptr;
    const float* U = nullptr; const float* bias = nullptr;
    for (int i = 0; i < n_in; ++i) {
        switch (in_sizes[i]) {
            case B_ * S_ * I_: x    = (const float*)d_in[i]; break;
            case I_ * G4H:     W    = (const float*)d_in[i]; break;
            case H_ * G4H:     U    = (const float*)d_in[i]; break;
            case G4H:          bias = (const float*)d_in[i]; break;
            default: break;
        }
    }
    if (!x && n_in > 0)    x    = (const float*)d_in[0];
    if (!W && n_in > 1)    W    = (const float*)d_in[1];
    if (!U && n_in > 2)    U    = (const float*)d_in[2];
    if (!bias && n_in > 3) bias = (const float*)d_in[3];

    cudaFuncSetAttribute(k_lstm, cudaFuncAttributeMaxDynamicSharedMemorySize,
                         SMEM_BYTES);
    k_init<<<(B_ * H_ + NTH - 1) / NTH, NTH>>>();
    k_lstm<<<GRID, NTH, SMEM_BYTES>>>(x, W, U, bias, (float*)d_out);
}

// round 11
// speedup vs baseline: 2.2338x; 1.1252x over previous
#include <cuda_runtime.h>
#include <cstdint>
#include <math.h>

#define B_   64
#define S_   512
#define I_   256
#define H_   512
#define G4H  2048
#define GRID 128
#define NTH  256

#define XCW  68           // x chunk row width (64 + 4 pad)
#define HW   516          // h row width (512 + 4 pad)

// SMEM float counts
#define F_WU 12288        // [768][16]
#define F_X  (2*64*XCW)   // 2 x [64][68]
#define F_H  (64*HW)      // [64][516]
#define F_G  (64*20)      // gate exchange
#define SMEM_FLOATS (F_WU + F_X + F_H + F_G)
#define SMEM_BYTES  (SMEM_FLOATS*4 + 64)

// ---------------- static device scratch ----------------
__device__ __align__(16) float g_xC[(size_t)S_ * 4 * 64 * XCW];  // [t][chunk][b][68]
__device__ __align__(16) float g_h[64 * HW];                     // [b][516] padded
__device__ unsigned g_bar_cnt = 0;
__device__ volatile unsigned g_bar_sense = 0;

// ---------------- PTX helpers ----------------
__device__ __forceinline__ unsigned sm2u(const void* p) {
    unsigned a;
    asm("{ .reg .u64 t; cvta.to.shared.u64 t, %1; cvt.u32.u64 %0, t; }" : "=r"(a) : "l"(p));
    return a;
}
__device__ __forceinline__ void mbar_init(unsigned a, unsigned c) {
    asm volatile("mbarrier.init.shared.b64 [%0], %1;" :: "r"(a), "r"(c) : "memory");
}
__device__ __forceinline__ void mbar_arrive_expect(unsigned a, unsigned bytes) {
    asm volatile("mbarrier.arrive.expect_tx.shared.b64 _, [%0], %1;"
                 :: "r"(a), "r"(bytes) : "memory");
}
__device__ __forceinline__ void bulk_g2s(unsigned dst, const void* src,
                                         unsigned bytes, unsigned mbar) {
    asm volatile("cp.async.bulk.shared::cluster.global.mbarrier::complete_tx::bytes "
                 "[%0], [%1], %2, [%3];"
                 :: "r"(dst), "l"(src), "r"(bytes), "r"(mbar) : "memory");
}
__device__ __forceinline__ void mbar_wait(unsigned a, unsigned ph) {
    unsigned done = 0;
    while (!done) {
        asm volatile("{ .reg .pred p; "
                     "mbarrier.try_wait.parity.acquire.cta.shared::cta.b64 p, [%1], %2, 0x989680; "
                     "selp.b32 %0, 1, 0, p; }"
                     : "=r"(done) : "r"(a), "r"(ph) : "memory");
    }
}
__device__ __forceinline__ void fma2(unsigned long long& acc,
                                     unsigned long long a, unsigned long long b) {
    asm("fma.rn.f32x2 %0, %1, %2, %0;" : "+l"(acc) : "l"(a), "l"(b));
}
// 4 k-steps: one activation float4 (1 batch) x 4 columns from SMEM weights
__device__ __forceinline__ void dot4(const float* __restrict__ ab,
                                     const float* __restrict__ wu,
                                     unsigned long long& a01, unsigned long long& a23) {
    float4 h4 = *reinterpret_cast<const float4*>(ab);
#pragma unroll
    for (int j = 0; j < 4; ++j) {
        float hv = (&h4.x)[j];
        unsigned long long hh;
        asm("mov.b64 %0, {%1, %1};" : "=l"(hh) : "f"(hv));
        ulonglong2 w = *reinterpret_cast<const ulonglong2*>(wu + j * 16);
        fma2(a01, hh, w.x);
        fma2(a23, hh, w.y);
    }
}

// ---------------- prep kernels ----------------
__global__ void k_init() {
    int i = blockIdx.x * blockDim.x + threadIdx.x;
    if (i < 64 * HW) g_h[i] = 0.0f;
}
// pack x[b][t][k] -> g_xC[t][chunk][b][68] (pad zero)
__global__ void k_xprep(const float* __restrict__ x) {
    int t = blockIdx.x;
    for (int i = threadIdx.x; i < 4 * 64 * XCW; i += NTH) {
        int c = i / (64 * XCW);
        int r = i - c * (64 * XCW);
        int b = r / XCW;
        int k = r - b * XCW;
        float v = (k < 64) ? x[((size_t)b * S_ + t) * I_ + c * 64 + k] : 0.0f;
        g_xC[(size_t)t * (4 * 64 * XCW) + i] = v;
    }
}

// ---------------- persistent LSTM ----------------
__global__ void __launch_bounds__(NTH, 1)
k_lstm(const float* __restrict__ W, const float* __restrict__ U,
       const float* __restrict__ bias, float* __restrict__ out) {
    extern __shared__ float sm[];
    float* sWU = sm;                  // [768][16]
    float* sX  = sm + F_WU;           // 2 x [64][68]
    float* sH  = sX + F_X;            // [64][516]
    float* sG  = sH + F_H;            // [64][20]
    unsigned long long* mb = reinterpret_cast<unsigned long long*>(sG + F_G);
    const unsigned mbX0 = sm2u(mb + 0), mbX1 = sm2u(mb + 1), mbH = sm2u(mb + 2);
    const unsigned sX_u = sm2u(sX), sH_u = sm2u(sH);

    const int tid = threadIdx.x;
    const int blk = blockIdx.x;
    const int b   = tid >> 2;         // batch 0..63
    const int cq  = tid & 3;          // gate 0..3
    const int bu  = tid >> 2;         // update batch
    const int jl  = tid & 3;          // update hidden sub-col
    const int hcol = blk * 4 + jl;
    float c_state = 0.0f;

    // ---- prologue ----
    if (tid == 0) {
        mbar_init(mbX0, 1); mbar_init(mbX1, 1); mbar_init(mbH, 1);
        asm volatile("fence.proxy.async.shared::cta;" ::: "memory");
    }
    // weights -> SMEM once: sWU[k][q*4+j] = WU[k][q*512 + blk*4 + j]
    for (int i = tid; i < 768 * 4; i += NTH) {
        int k = i >> 2, q = i & 3;
        int col = q * H_ + blk * 4;
        float4 w = (k < I_)
            ? *reinterpret_cast<const float4*>(W + (size_t)k * G4H + col)
            : *reinterpret_cast<const float4*>(U + (size_t)(k - I_) * G4H + col);
        *reinterpret_cast<float4*>(sWU + k * 16 + q * 4) = w;
    }
    unsigned long long bias01, bias23;
    {
        float4 bv = *reinterpret_cast<const float4*>(bias + cq * H_ + blk * 4);
        asm("mov.b64 %0, {%1, %2};" : "=l"(bias01) : "f"(bv.x), "f"(bv.y));
        asm("mov.b64 %0, {%1, %2};" : "=l"(bias23) : "f"(bv.z), "f"(bv.w));
    }
    __syncthreads();

    // prologue: issue x chunks 0,1 (t=0)
    if (tid == 0) {
        mbar_arrive_expect(mbX0, 64 * XCW * 4);
        bulk_g2s(sX_u, g_xC, 64 * XCW * 4, mbX0);
        mbar_arrive_expect(mbX1, 64 * XCW * 4);
        bulk_g2s(sX_u + 64 * XCW * 4, g_xC + 64 * XCW, 64 * XCW * 4, mbX1);
    }
    unsigned phx[2] = {0u, 0u};

    for (int t = 0; t < S_; ++t) {
        // ---- ONE h bulk copy (132KB); sH free & g_h complete past grid barrier ----
        if (tid == 0) {
            mbar_arrive_expect(mbH, 64 * HW * 4);
            bulk_g2s(sH_u, g_h, 64 * HW * 4, mbH);
        }

        unsigned long long a01 = bias01, a23 = bias23;

        // ---- x-part: 4 chunks of 64 k, 2-buffer ring ----
#pragma unroll
        for (int c = 0; c < 4; ++c) {
            const int m = c & 1;
            mbar_wait(m ? mbX1 : mbX0, phx[m]); phx[m] ^= 1u;
            const float* xb = sX + m * (64 * XCW) + b * XCW;
            const float* wu = sWU + (c * 64) * 16 + cq * 4;
#pragma unroll 4
            for (int kk = 0; kk < 64; kk += 4)
                dot4(xb + kk, wu + kk * 16, a01, a23);
            __syncthreads();                      // buffer m drained
            int g2 = 4 * t + c + 2;               // refill 2 ahead
            if (tid == 0 && g2 < 4 * S_) {
                unsigned mbx = m ? mbX1 : mbX0;
                mbar_arrive_expect(mbx, 64 * XCW * 4);
                bulk_g2s(sX_u + (unsigned)(m * 64 * XCW * 4),
                         g_xC + (size_t)g2 * (64 * XCW), 64 * XCW * 4, mbx);
            }
        }

        // ---- h-part: 512 k ----
        mbar_wait(mbH, (unsigned)(t & 1));
        {
            const float* hb = sH + b * HW;
            const float* wu = sWU + I_ * 16 + cq * 4;
#pragma unroll 4
            for (int kk = 0; kk < H_; kk += 4)
                dot4(hb + kk, wu + kk * 16, a01, a23);
        }

        // ---- gate exchange ----
        float4 gv;
        asm("mov.b64 {%0, %1}, %2;" : "=f"(gv.x), "=f"(gv.y) : "l"(a01));
        asm("mov.b64 {%0, %1}, %2;" : "=f"(gv.z), "=f"(gv.w) : "l"(a23));
        *reinterpret_cast<float4*>(sG + b * 20 + cq * 4) = gv;
        __syncthreads();

        // ---- cell update ----
        {
            float gi = sG[bu * 20 + 0  + jl];
            float gf = sG[bu * 20 + 4  + jl];
            float gg = sG[bu * 20 + 8  + jl];
            float go = sG[bu * 20 + 12 + jl];
            float iv = 1.0f / (1.0f + expf(-gi));
            float fv = 1.0f / (1.0f + expf(-gf));
            float gt = tanhf(gg);
            float ov = 1.0f / (1.0f + expf(-go));
            c_state = fv * c_state + iv * gt;
            float hv = ov * tanhf(c_state);

            g_h[bu * HW + hcol] = hv;
            out[((size_t)bu * S_ + t) * H_ + hcol] = hv;
            if (t == S_ - 1) {
                size_t base = (size_t)B_ * S_ * H_;
                out[base + (size_t)bu * H_ + hcol] = hv;
                out[base + (size_t)B_ * H_ + (size_t)bu * H_ + hcol] = c_state;
            }
        }

        // ---- grid barrier ----
        __syncthreads();
        if (tid == 0) {
            __threadfence();
            unsigned want = (unsigned)((t & 1) ^ 1);
            if (atomicAdd(&g_bar_cnt, 1u) == GRID - 1) {
                atomicExch(&g_bar_cnt, 0u);
                __threadfence();
                g_bar_sense = want;
            } else {
                while (g_bar_sense != want) { }
            }
            __threadfence();
        }
        __syncthreads();
    }
}

// ---------------- launch ----------------
extern "C" void kernel_launch(void* const* d_in, const int* in_sizes, int n_in,
                              void* d_out, int out_size) {
    const float* x = nullptr; const float* W = nullptr;
    const float* U = nullptr; const float* bias = nullptr;
    for (int i = 0; i < n_in; ++i) {
        switch (in_sizes[i]) {
            case B_ * S_ * I_: x    = (const float*)d_in[i]; break;
            case I_ * G4H:     W    = (const float*)d_in[i]; break;
            case H_ * G4H:     U    = (const float*)d_in[i]; break;
            case G4H:          bias = (const float*)d_in[i]; break;
            default: break;
        }
    }
    if (!x && n_in > 0)    x    = (const float*)d_in[0];
    if (!W && n_in > 1)    W    = (const float*)d_in[1];
    if (!U && n_in > 2)    U    = (const float*)d_in[2];
    if (!bias && n_in > 3) bias = (const float*)d_in[3];

    cudaFuncSetAttribute(k_lstm, cudaFuncAttributeMaxDynamicSharedMemorySize,
                         SMEM_BYTES);
    k_init<<<(64 * HW + NTH - 1) / NTH, NTH>>>();
    k_xprep<<<S_, NTH>>>(x);
    k_lstm<<<GRID, NTH, SMEM_BYTES>>>(W, U, bias, (float*)d_out);
}

// round 13
// speedup vs baseline: 2.6699x; 1.1952x over previous
#include <cuda_runtime.h>
#include <cstdint>
#include <math.h>

#define B_   64
#define S_   512
#define I_   256
#define H_   512
#define G4H  2048
#define GRID 128
#define NTH  256

#define HCW  132          // h chunk row width (128 + 4 pad)

// SMEM float counts (recurrent kernel)
#define F_U   (512*16)        // U weights [512][16]            32768 B
#define F_H   (4*64*HCW)      // 4 chunks x [64][132]          135168 B
#define F_XP  (4*64*16)       // 4-slot xp ring [64][16]        16384 B
#define F_G   (64*20)         // gate exchange                   5120 B
#define SMEM_FLOATS (F_U + F_H + F_XP + F_G)
#define SMEM_BYTES  (SMEM_FLOATS*4 + 64)

// ---------------- static device scratch ----------------
__device__ __align__(256) float g_xp[(size_t)S_ * GRID * B_ * 16]; // [t][blk][b][16] = 256MB
__device__ __align__(256) float g_h[4 * B_ * HCW];                 // [chunk][b][132]
__device__ unsigned g_bar_cnt = 0;
__device__ volatile unsigned g_bar_sense = 0;

// ---------------- PTX helpers ----------------
__device__ __forceinline__ unsigned sm2u(const void* p) {
    unsigned a;
    asm("{ .reg .u64 t; cvta.to.shared.u64 t, %1; cvt.u32.u64 %0, t; }" : "=r"(a) : "l"(p));
    return a;
}
__device__ __forceinline__ void mbar_init(unsigned a, unsigned c) {
    asm volatile("mbarrier.init.shared.b64 [%0], %1;" :: "r"(a), "r"(c) : "memory");
}
__device__ __forceinline__ void mbar_arrive_expect(unsigned a, unsigned bytes) {
    asm volatile("mbarrier.arrive.expect_tx.shared.b64 _, [%0], %1;"
                 :: "r"(a), "r"(bytes) : "memory");
}
__device__ __forceinline__ void bulk_g2s(unsigned dst, const void* src,
                                         unsigned bytes, unsigned mbar) {
    asm volatile("cp.async.bulk.shared::cluster.global.mbarrier::complete_tx::bytes "
                 "[%0], [%1], %2, [%3];"
                 :: "r"(dst), "l"(src), "r"(bytes), "r"(mbar) : "memory");
}
__device__ __forceinline__ void mbar_wait(unsigned a, unsigned ph) {
    unsigned done = 0;
    while (!done) {
        asm volatile("{ .reg .pred p; "
                     "mbarrier.try_wait.parity.acquire.cta.shared::cta.b64 p, [%1], %2, 0x989680; "
                     "selp.b32 %0, 1, 0, p; }"
                     : "=r"(done) : "r"(a), "r"(ph) : "memory");
    }
}
__device__ __forceinline__ void fma2(unsigned long long& acc,
                                     unsigned long long a, unsigned long long b) {
    asm("fma.rn.f32x2 %0, %1, %2, %0;" : "+l"(acc) : "l"(a), "l"(b));
}
// 4 k-steps: one activation float4 (1 batch) x 4 columns from SMEM weights
__device__ __forceinline__ void dot4(const float* __restrict__ ab,
                                     const float* __restrict__ wu,
                                     unsigned long long& a01, unsigned long long& a23) {
    float4 h4 = *reinterpret_cast<const float4*>(ab);
#pragma unroll
    for (int j = 0; j < 4; ++j) {
        float hv = (&h4.x)[j];
        unsigned long long hh;
        asm("mov.b64 %0, {%1, %1};" : "=l"(hh) : "f"(hv));
        ulonglong2 w = *reinterpret_cast<const ulonglong2*>(wu + j * 16);
        fma2(a01, hh, w.x);
        fma2(a23, hh, w.y);
    }
}

// ---------------- init: zero h state ----------------
__global__ void k_init() {
    int i = blockIdx.x * blockDim.x + threadIdx.x;
    if (i < 4 * B_ * HCW) g_h[i] = 0.0f;
}

// ---------------- x-projection GEMM: g_xp = x @ W + bias ----------------
// M = B*S = 32768 (m = b*512 + t), N = 2048, K = 256.
// 128x128 tile, 256 threads, 8x8 per thread, K-chunk 16.
__global__ void __launch_bounds__(256, 2)
k_xproj(const float* __restrict__ x, const float* __restrict__ W,
        const float* __restrict__ bias) {
    __shared__ float As[16][132];   // [k][m-local]
    __shared__ float Bs[16][128];   // [k][n-local]
    const int tid = threadIdx.x;
    const int tx = tid & 15, ty = tid >> 4;
    const int m0 = blockIdx.x * 128;
    const int n0 = blockIdx.y * 128;

    float acc[8][8];
#pragma unroll
    for (int r = 0; r < 8; ++r)
#pragma unroll
        for (int c = 0; c < 8; ++c) acc[r][c] = 0.0f;

    for (int k0 = 0; k0 < I_; k0 += 16) {
        __syncthreads();
        // A tile: 128 rows x 16 k (transpose into [k][m])
#pragma unroll
        for (int i = tid; i < 512; i += 256) {
            int r = i >> 2, g = i & 3;
            float4 v = *reinterpret_cast<const float4*>(
                x + (size_t)(m0 + r) * I_ + k0 + g * 4);
            As[g * 4 + 0][r] = v.x; As[g * 4 + 1][r] = v.y;
            As[g * 4 + 2][r] = v.z; As[g * 4 + 3][r] = v.w;
        }
        // B tile: 16 k x 128 n
#pragma unroll
        for (int i = tid; i < 512; i += 256) {
            int kk = i >> 5, g = i & 31;
            *reinterpret_cast<float4*>(&Bs[kk][g * 4]) =
                *reinterpret_cast<const float4*>(W + (size_t)(k0 + kk) * G4H + n0 + g * 4);
        }
        __syncthreads();
#pragma unroll
        for (int kk = 0; kk < 16; ++kk) {
            float a[8], bf[8];
            *reinterpret_cast<float4*>(a)     = *reinterpret_cast<float4*>(&As[kk][ty * 8]);
            *reinterpret_cast<float4*>(a + 4) = *reinterpret_cast<float4*>(&As[kk][ty * 8 + 4]);
            *reinterpret_cast<float4*>(bf)     = *reinterpret_cast<float4*>(&Bs[kk][tx * 4]);
            *reinterpret_cast<float4*>(bf + 4) = *reinterpret_cast<float4*>(&Bs[kk][tx * 4 + 64]);
#pragma unroll
            for (int r = 0; r < 8; ++r)
#pragma unroll
                for (int c = 0; c < 8; ++c)
                    acc[r][c] = fmaf(a[r], bf[c], acc[r][c]);
        }
    }

    // epilogue: +bias, scatter to g_xp[t][blk][b][q*4+jl]
    const int b  = m0 >> 9;           // batch (tile never crosses b: 128 | 512)
    const int tb = (m0 & 511) + ty * 8;
    float4 bias0 = *reinterpret_cast<const float4*>(bias + n0 + tx * 4);
    float4 bias1 = *reinterpret_cast<const float4*>(bias + n0 + tx * 4 + 64);
#pragma unroll
    for (int r = 0; r < 8; ++r) {
        int t = tb + r;
#pragma unroll
        for (int grp = 0; grp < 2; ++grp) {
            int n  = n0 + tx * 4 + grp * 64;
            int q  = n >> 9;
            int cg = (n & 511) >> 2;
            float4 v;
            v.x = acc[r][grp * 4 + 0] + (grp ? bias1.x : bias0.x);
            v.y = acc[r][grp * 4 + 1] + (grp ? bias1.y : bias0.y);
            v.z = acc[r][grp * 4 + 2] + (grp ? bias1.z : bias0.z);
            v.w = acc[r][grp * 4 + 3] + (grp ? bias1.w : bias0.w);
            *reinterpret_cast<float4*>(
                g_xp + (((size_t)t * GRID + cg) * B_ + b) * 16 + q * 4) = v;
        }
    }
}

// ---------------- persistent recurrent kernel ----------------
__global__ void __launch_bounds__(NTH, 1)
k_lstm(const float* __restrict__ U, float* __restrict__ out) {
    extern __shared__ float sm[];
    float* sU  = sm;                  // [512][16]
    float* sH  = sm + F_U;            // 4 x [64][132]
    float* sXP = sH + F_H;            // 4 x [64][16]
    float* sG  = sXP + F_XP;          // [64][20]
    unsigned long long* mb = reinterpret_cast<unsigned long long*>(sG + F_G);
    const unsigned mbH0  = sm2u(mb);        // +8*c
    const unsigned mbXP0 = sm2u(mb + 4);    // +8*s
    const unsigned sH_u  = sm2u(sH);
    const unsigned sXP_u = sm2u(sXP);

    const int tid = threadIdx.x;
    const int blk = blockIdx.x;
    const int b   = tid >> 2;         // batch 0..63
    const int cq  = tid & 3;          // gate 0..3
    const int bu  = tid >> 2;
    const int jl  = tid & 3;
    const int hcol = blk * 4 + jl;
    const int hchk = blk >> 5;        // which h k-chunk this CTA's columns live in
    const int hloc = hcol & 127;
    float c_state = 0.0f;

    // ---- prologue ----
    if (tid == 0) {
#pragma unroll
        for (int i = 0; i < 8; ++i) mbar_init(mbH0 + i * 8, 1);
        asm volatile("fence.proxy.async.shared::cta;" ::: "memory");
    }
    // U -> SMEM once: sU[k][q*4+j] = U[k][q*512 + blk*4 + j]
    for (int i = tid; i < 512 * 4; i += NTH) {
        int k = i >> 2, q = i & 3;
        float4 w = *reinterpret_cast<const float4*>(
            U + (size_t)k * G4H + q * H_ + blk * 4);
        *reinterpret_cast<float4*>(sU + k * 16 + q * 4) = w;
    }
    __syncthreads();
    if (tid == 0) {   // prefetch xp slots for t = 0..3
#pragma unroll
        for (int s = 0; s < 4; ++s) {
            mbar_arrive_expect(mbXP0 + s * 8, 4096);
            bulk_g2s(sXP_u + (unsigned)(s * 4096),
                     g_xp + ((size_t)s * GRID + blk) * (B_ * 16), 4096, mbXP0 + s * 8);
        }
    }

    for (int t = 0; t < S_; ++t) {
        // ---- issue 4 h-chunk copies (33 KB each, contiguous) ----
        if (tid == 0) {
#pragma unroll
            for (int c = 0; c < 4; ++c) {
                mbar_arrive_expect(mbH0 + c * 8, 64 * HCW * 4);
                bulk_g2s(sH_u + (unsigned)(c * 64 * HCW * 4),
                         g_h + c * (64 * HCW), 64 * HCW * 4, mbH0 + c * 8);
            }
        }

        // ---- accumulator init from x_proj slice ----
        const int s = t & 3;
        mbar_wait(mbXP0 + (unsigned)(s * 8), (unsigned)((t >> 2) & 1));
        unsigned long long a01, a23;
        {
            float4 xin = *reinterpret_cast<const float4*>(sXP + s * (64 * 16) + b * 16 + cq * 4);
            asm("mov.b64 %0, {%1, %2};" : "=l"(a01) : "f"(xin.x), "f"(xin.y));
            asm("mov.b64 %0, {%1, %2};" : "=l"(a23) : "f"(xin.z), "f"(xin.w));
        }

        // ---- h-part: 4 pipelined k-chunks of 128 ----
#pragma unroll
        for (int c = 0; c < 4; ++c) {
            mbar_wait(mbH0 + (unsigned)(c * 8), (unsigned)(t & 1));
            const float* hb = sH + c * (64 * HCW) + b * HCW;
            const float* wu = sU + (c * 128) * 16 + cq * 4;
#pragma unroll 4
            for (int kk = 0; kk < 128; kk += 4)
                dot4(hb + kk, wu + kk * 16, a01, a23);
        }

        // ---- gate exchange ----
        float4 gv;
        asm("mov.b64 {%0, %1}, %2;" : "=f"(gv.x), "=f"(gv.y) : "l"(a01));
        asm("mov.b64 {%0, %1}, %2;" : "=f"(gv.z), "=f"(gv.w) : "l"(a23));
        *reinterpret_cast<float4*>(sG + b * 20 + cq * 4) = gv;
        __syncthreads();

        // refill xp slot s with t+4 (all threads past their sXP read)
        if (tid == 0 && t + 4 < S_) {
            mbar_arrive_expect(mbXP0 + (unsigned)(s * 8), 4096);
            bulk_g2s(sXP_u + (unsigned)(s * 4096),
                     g_xp + ((size_t)(t + 4) * GRID + blk) * (B_ * 16), 4096,
                     mbXP0 + (unsigned)(s * 8));
        }

        // ---- cell update ----
        {
            float gi = sG[bu * 20 + 0  + jl];
            float gf = sG[bu * 20 + 4  + jl];
            float gg = sG[bu * 20 + 8  + jl];
            float go = sG[bu * 20 + 12 + jl];
            float iv = 1.0f / (1.0f + expf(-gi));
            float fv = 1.0f / (1.0f + expf(-gf));
            float gt = tanhf(gg);
            float ov = 1.0f / (1.0f + expf(-go));
            c_state = fv * c_state + iv * gt;
            float hv = ov * tanhf(c_state);

            g_h[(hchk * B_ + bu) * HCW + hloc] = hv;
            out[((size_t)bu * S_ + t) * H_ + hcol] = hv;
            if (t == S_ - 1) {
                size_t base = (size_t)B_ * S_ * H_;
                out[base + (size_t)bu * H_ + hcol] = hv;
                out[base + (size_t)B_ * H_ + (size_t)bu * H_ + hcol] = c_state;
            }
        }

        // ---- grid barrier ----
        __syncthreads();
        if (tid == 0) {
            __threadfence();
            unsigned want = (unsigned)((t & 1) ^ 1);
            if (atomicAdd(&g_bar_cnt, 1u) == GRID - 1) {
                atomicExch(&g_bar_cnt, 0u);
                __threadfence();
                g_bar_sense = want;
            } else {
                while (g_bar_sense != want) { }
            }
            __threadfence();
        }
        __syncthreads();
    }
}

// ---------------- launch ----------------
extern "C" void kernel_launch(void* const* d_in, const int* in_sizes, int n_in,
                              void* d_out, int out_size) {
    const float* x = nullptr; const float* W = nullptr;
    const float* U = nullptr; const float* bias = nullptr;
    for (int i = 0; i < n_in; ++i) {
        switch (in_sizes[i]) {
            case B_ * S_ * I_: x    = (const float*)d_in[i]; break;
            case I_ * G4H:     W    = (const float*)d_in[i]; break;
            case H_ * G4H:     U    = (const float*)d_in[i]; break;
            case G4H:          bias = (const float*)d_in[i]; break;
            default: break;
        }
    }
    if (!x && n_in > 0)    x    = (const float*)d_in[0];
    if (!W && n_in > 1)    W    = (const float*)d_in[1];
    if (!U && n_in > 2)    U    = (const float*)d_in[2];
    if (!bias && n_in > 3) bias = (const float*)d_in[3];

    cudaFuncSetAttribute(k_lstm, cudaFuncAttributeMaxDynamicSharedMemorySize,
                         SMEM_BYTES);
    k_init<<<(4 * B_ * HCW + NTH - 1) / NTH, NTH>>>();
    k_xproj<<<dim3((B_ * S_) / 128, G4H / 128), 256>>>(x, W, bias);
    k_lstm<<<GRID, NTH, SMEM_BYTES>>>(U, (float*)d_out);
}